// round 14
// baseline (speedup 1.0000x reference)
#include <cuda_runtime.h>
#include <cuda_fp16.h>
#include <cstdint>

// ============================================================================
// LIIF sampler, single-pass fp16 mma.sync. Round 14: R9 structure with K=128
// W chunks (7 phases total instead of 14): L0 = one 80-row chunk, L1..3 = two
// 128-row chunks each. 2-deep per-group rings, bar->issue->wait1 order.
// oacc overlaid on each group's own (dead) W ring.
// ============================================================================

#define HQv 384
#define WQv 384
#define HFv 48
#define WFv 48

#define MT  128
#define NTH 512

// smem layout (bytes)
#define A_OFF 0                            // 128*528 = 67584
#define WRING_OFF 67584
#define GBUF  18432                        // 128 rows * 144B
#define GRING (2 * GBUF)                   // 36864 per group (2-deep)
#define BIAS_OFF (WRING_OFF + 4 * GRING)   // 215040
#define W4_OFF   (BIAS_OFF + 4096)         // 219136
#define B4_OFF   (W4_OFF + 3072)           // 222208
#define SMEM_TOTAL (B4_OFF + 16)           // 222224

// weight blob: per layer one fp16 plane [kpad][256]. kpad: L0=128, L1..3=256.
__device__ __align__(128) unsigned char g_wblob[458752];
__constant__ int c_lbase[4] = {0, 65536, 196608, 327680};

// ---------------------------------------------------------------------------
__device__ __forceinline__ uint32_t smem_u32(const void* p) {
    uint32_t a;
    asm("{ .reg .u64 t; cvta.to.shared.u64 t, %1; cvt.u32.u64 %0, t; }"
        : "=r"(a) : "l"(p));
    return a;
}
__device__ __forceinline__ void ldsm4(uint32_t* r, uint32_t a) {
    asm volatile("ldmatrix.sync.aligned.m8n8.x4.shared.b16 {%0,%1,%2,%3}, [%4];"
                 : "=r"(r[0]), "=r"(r[1]), "=r"(r[2]), "=r"(r[3]) : "r"(a));
}
__device__ __forceinline__ void ldsm4t(uint32_t* r, uint32_t a) {
    asm volatile("ldmatrix.sync.aligned.m8n8.x4.trans.shared.b16 {%0,%1,%2,%3}, [%4];"
                 : "=r"(r[0]), "=r"(r[1]), "=r"(r[2]), "=r"(r[3]) : "r"(a));
}
__device__ __forceinline__ void mma16816h(float* d, const uint32_t* a,
                                          uint32_t b0, uint32_t b1) {
    asm volatile(
        "mma.sync.aligned.m16n8k16.row.col.f32.f16.f16.f32 "
        "{%0,%1,%2,%3}, {%4,%5,%6,%7}, {%8,%9}, {%0,%1,%2,%3};"
        : "+f"(d[0]), "+f"(d[1]), "+f"(d[2]), "+f"(d[3])
        : "r"(a[0]), "r"(a[1]), "r"(a[2]), "r"(a[3]), "r"(b0), "r"(b1));
}
__device__ __forceinline__ void cpasync16(uint32_t dst, const void* src) {
    asm volatile("cp.async.cg.shared.global [%0], [%1], 16;"
                 :: "r"(dst), "l"(src) : "memory");
}
__device__ __forceinline__ void cp_commit() {
    asm volatile("cp.async.commit_group;" ::: "memory");
}
__device__ __forceinline__ uint32_t cvt1h(float a, float b) {
    __half ah = __float2half_rn(a), bh = __float2half_rn(b);
    return (uint32_t)__half_as_ushort(ah) | ((uint32_t)__half_as_ushort(bh) << 16);
}

// global chunk index g (0..6): g0 = L0 (80 rows), g1..6 = 128-row chunks
__device__ __forceinline__ void chunk_of(int g, int& layer, int& c, int& rows) {
    if (g == 0) { layer = 0; c = 0; rows = 80; }
    else { layer = 1 + (g - 1) / 2; c = (g - 1) & 1; rows = 128; }
}

// stage this group's 64-col slice of chunk g into ring buffer (g & 1)
__device__ __forceinline__ void issue_group_chunk(uint32_t sb, int tid, int grp, int g) {
    int layer, c, rows;
    chunk_of(g, layer, c, rows);
    const unsigned char* src0 = g_wblob + c_lbase[layer]
                              + (size_t)c * 128 * 512 + (size_t)grp * 128;
    const int t = tid & 127;
#pragma unroll
    for (int it = 0; it < 8; it++) {
        const int i = t + it * 128;   // 0..1023
        const int r = i >> 3, s = i & 7;
        if (r < rows)
            cpasync16(sb + WRING_OFF + grp * GRING + (g & 1) * GBUF + r * 144 + s * 16,
                      src0 + (size_t)r * 512 + s * 16);
    }
    cp_commit();
}

// ---------------------------------------------------------------------------
// Prep: W0..W3 fp32 -> single fp16 plane each.
// ---------------------------------------------------------------------------
__global__ void liif_prep_kernel(const float* __restrict__ W0, const float* __restrict__ W1,
                                 const float* __restrict__ W2, const float* __restrict__ W3)
{
    const int row = blockIdx.x;
    const int n = threadIdx.x;
    int layer, k;
    if (row < 128) { layer = 0; k = row; }
    else { layer = 1 + (row - 128) / 256; k = (row - 128) & 255; }
    const float* W = (layer == 0) ? W0 : (layer == 1) ? W1 : (layer == 2) ? W2 : W3;
    const int Kl = (layer == 0) ? 71 : 256;
    const float val = (k < Kl) ? W[k * 256 + n] : 0.0f;
    *(unsigned short*)(g_wblob + c_lbase[layer] + (size_t)k * 512 + n * 2) =
        __half_as_ushort(__float2half_rn(val));
}

// ---------------------------------------------------------------------------
__global__ __launch_bounds__(NTH, 1)
void liif_hmma_kernel(
    const float* __restrict__ x, const float* __restrict__ coord,
    const float* __restrict__ cell, const float* __restrict__ lr,
    const float* __restrict__ b0, const float* __restrict__ b1,
    const float* __restrict__ b2, const float* __restrict__ b3,
    const float* __restrict__ W4, const float* __restrict__ b4,
    float* __restrict__ out)
{
    extern __shared__ __align__(16) char smem[];
    const uint32_t sb = smem_u32(smem);
    const int tid = threadIdx.x;
    const int lane = tid & 31;
    const int wid = tid >> 5;
    const int wm = wid & 3;     // 4 warps along M (32 rows each)
    const int grp = wid >> 2;   // column group 0..3 (64 cols); 1 warp/SMSP/group

    float* bias_s = (float*)(smem + BIAS_OFF);
    float* w4_s   = (float*)(smem + W4_OFF);
    float* b4_s   = (float*)(smem + B4_OFF);

    // prefetch this group's first W chunk (lands during gather)
    issue_group_chunk(sb, tid, grp, 0);

    // stage biases + W4
    if (tid < 256) {
        bias_s[tid] = b0[tid]; bias_s[256 + tid] = b1[tid];
        bias_s[512 + tid] = b2[tid]; bias_s[768 + tid] = b3[tid];
    }
    for (int i = tid; i < 768; i += NTH) w4_s[i] = W4[i];
    if (tid < 3) b4_s[tid] = b4[tid];

    // ---- gather -> A0 (fp16, 128 point-rows, stride 528B) ----
    const int p  = tid & 127;
    const int q  = tid >> 7;   // 0..3
    const int gp = blockIdx.x * MT + p;
    const int b  = gp / (HQv * WQv);
    const int rem = gp % (HQv * WQv);
    const int yq = rem / WQv, xq = rem % WQv;
    const float gy = coord[((size_t)(b * HQv + yq) * WQv + xq) * 2 + 0];
    const float gx = coord[((size_t)(b * HQv + yq) * WQv + xq) * 2 + 1];

    float tx = __fmul_rn(__fadd_rn(__fmul_rn(__fadd_rn(gx, 1.0f), (float)WFv), -1.0f), 0.5f);
    float ty = __fmul_rn(__fadd_rn(__fmul_rn(__fadd_rn(gy, 1.0f), (float)HFv), -1.0f), 0.5f);
    const int ixn = (int)rintf(tx);
    const int iyn = (int)rintf(ty);
    const bool valid = (ixn >= 0) && (ixn < WFv) && (iyn >= 0) && (iyn < HFv);
    const int ixc = min(max(ixn, 0), WFv - 1);
    const int iyc = min(max(iyn, 0), HFv - 1);

    if (q < 2) {   // channels q*32 .. q*32+31
        const float* xb = x + (size_t)b * 64 * (HFv * WFv) + (size_t)iyc * WFv + ixc;
        char* rh = smem + A_OFF + (size_t)p * 528 + q * 64;
#pragma unroll
        for (int j = 0; j < 16; j++) {
            const int c0 = q * 32 + 2 * j;
            const float f0 = valid ? xb[(size_t)c0 * (HFv * WFv)] : 0.0f;
            const float f1 = valid ? xb[(size_t)(c0 + 1) * (HFv * WFv)] : 0.0f;
            *(uint32_t*)(rh + j * 4) = cvt1h(f0, f1);
        }
    } else if (q == 2) {  // scalar features -> cols 64..79 (kpad=80)
        float qy = 0.0f, qx = 0.0f;
        if (valid) {
            qy = __fadd_rn(__fdiv_rn(__fadd_rn(__fmul_rn(2.0f, (float)iyc), 1.0f), (float)HFv), -1.0f);
            qx = __fadd_rn(__fdiv_rn(__fadd_rn(__fmul_rn(2.0f, (float)ixc), 1.0f), (float)WFv), -1.0f);
        }
        float vals[16];
#pragma unroll
        for (int i = 0; i < 16; i++) vals[i] = 0.0f;
        vals[0] = __fmul_rn(__fadd_rn(gy, -qy), (float)HFv);
        vals[1] = __fmul_rn(__fadd_rn(gx, -qx), (float)WFv);
        vals[2] = __fmul_rn(cell[b * 2 + 0], (float)HFv);
        vals[3] = __fmul_rn(cell[b * 2 + 1], (float)WFv);
        const float rx = 1.0f / (float)HFv, ry = 1.0f / (float)WFv;
        const float lo_c = -1.0f + 1e-6f, hi_c = 1.0f - 1e-6f;
        float s[3][4];
        int j = 0;
#pragma unroll
        for (int a = 0; a < 2; a++) {
#pragma unroll
            for (int c2 = 0; c2 < 2; c2++) {
                const float vx = a ? 1.0f : -1.0f;
                const float vy = c2 ? 1.0f : -1.0f;
                float cy = __fadd_rn(__fadd_rn(gy, __fmul_rn(vx, rx)), 1e-6f);
                float cx = __fadd_rn(__fadd_rn(gx, __fmul_rn(vy, ry)), 1e-6f);
                cy = fminf(fmaxf(cy, lo_c), hi_c);
                cx = fminf(fmaxf(cx, lo_c), hi_c);
                float fx = __fmul_rn(__fadd_rn(__fmul_rn(__fadd_rn(cx, 1.0f), (float)WFv), -1.0f), 0.5f);
                float fy = __fmul_rn(__fadd_rn(__fmul_rn(__fadd_rn(cy, 1.0f), (float)HFv), -1.0f), 0.5f);
                int jx = min(max((int)rintf(fx), 0), WFv - 1);
                int jy = min(max((int)rintf(fy), 0), HFv - 1);
#pragma unroll
                for (int ch = 0; ch < 3; ch++)
                    s[ch][j] = lr[((size_t)(b * 3 + ch) * HFv + jy) * WFv + jx];
                j++;
            }
        }
#pragma unroll
        for (int ch = 0; ch < 3; ch++) {
            const float m = 0.25f * (s[ch][0] + s[ch][1] + s[ch][2] + s[ch][3]);
            float v = 0.0f;
#pragma unroll
            for (int qq = 0; qq < 4; qq++) { const float d = s[ch][qq] - m; v += d * d; }
            vals[4 + ch] = sqrtf(v * (1.0f / 3.0f));
        }
        char* rh = smem + A_OFF + (size_t)p * 528 + 128;
#pragma unroll
        for (int k = 0; k < 8; k++)
            *(uint32_t*)(rh + k * 4) = cvt1h(vals[2 * k], vals[2 * k + 1]);
    }
    __syncthreads();

    // ---- 4 MMA layers, group-decoupled phases, K=128 chunks (7 total) ----
    float acc[2][8][4];
    const uint32_t aRowByte = (uint32_t)(wm * 32 + (lane & 15)) * 528 + (lane >> 4) * 16;
    const uint32_t wRowByte = (uint32_t)(lane & 15) * 144;
    const uint32_t wColByte = (uint32_t)(lane >> 4) * 16;
    const uint32_t wbg = sb + WRING_OFF + grp * GRING;
    const uint32_t barid = 1 + grp;

    int g = 0;  // global chunk index (0..6)
#pragma unroll 1
    for (int layer = 0; layer < 4; layer++) {
        const int nch = (layer == 0) ? 1 : 2;
#pragma unroll
        for (int mt = 0; mt < 2; mt++)
#pragma unroll
            for (int nt = 0; nt < 8; nt++)
#pragma unroll
                for (int e = 0; e < 4; e++) acc[mt][nt][e] = 0.0f;

#pragma unroll 1
        for (int c = 0; c < nch; c++, g++) {
            // group barrier: all group threads finished the buffer issue will overwrite
            asm volatile("bar.sync %0, 128;" :: "r"(barid) : "memory");
            if (g + 1 < 7) {
                issue_group_chunk(sb, tid, grp, g + 1);
                asm volatile("cp.async.wait_group 1;" ::: "memory");
            } else {
                asm volatile("cp.async.wait_group 0;" ::: "memory");
            }

            const uint32_t wBase = wbg + (g & 1) * GBUF + wRowByte + wColByte;
            const uint32_t aBase = sb + A_OFF + aRowByte + (uint32_t)(c * 128) * 2;
            const int ks = (g == 0) ? 5 : 8;
#pragma unroll 1
            for (int kk = 0; kk < ks; kk++) {
                const uint32_t kByte = (uint32_t)(kk * 16) * 2;
                uint32_t ah[2][4];
                ldsm4(ah[0], aBase + kByte);
                ldsm4(ah[1], aBase + 16 * 528 + kByte);
#pragma unroll
                for (int ng = 0; ng < 4; ng++) {
                    const uint32_t bo = (uint32_t)(kk * 16) * 144 + (uint32_t)ng * 32;
                    uint32_t w[4];
                    ldsm4t(w, wBase + bo);
                    mma16816h(acc[0][2 * ng],     ah[0], w[0], w[1]);
                    mma16816h(acc[0][2 * ng + 1], ah[0], w[2], w[3]);
                    mma16816h(acc[1][2 * ng],     ah[1], w[0], w[1]);
                    mma16816h(acc[1][2 * ng + 1], ah[1], w[2], w[3]);
                }
            }
        }

        __syncthreads();   // all groups done reading A
        const float* bl_bias = bias_s + layer * 256;
        if (layer < 3) {
            // epilogue: relu(D+b) -> fp16 back into A (in place)
#pragma unroll
            for (int mt = 0; mt < 2; mt++) {
#pragma unroll
                for (int nt = 0; nt < 8; nt++) {
                    const int r0 = wm * 32 + mt * 16 + (lane >> 2);
                    const int c0 = grp * 64 + nt * 8 + (lane & 3) * 2;
                    const float bb0 = bl_bias[c0], bb1 = bl_bias[c0 + 1];
                    const float h00 = fmaxf(acc[mt][nt][0] + bb0, 0.0f);
                    const float h01 = fmaxf(acc[mt][nt][1] + bb1, 0.0f);
                    const float h10 = fmaxf(acc[mt][nt][2] + bb0, 0.0f);
                    const float h11 = fmaxf(acc[mt][nt][3] + bb1, 0.0f);
                    *(uint32_t*)(smem + A_OFF + (size_t)r0 * 528 + c0 * 2) = cvt1h(h00, h01);
                    *(uint32_t*)(smem + A_OFF + (size_t)(r0 + 8) * 528 + c0 * 2) = cvt1h(h10, h11);
                }
            }
            __syncthreads();   // A ready for next layer (all groups)
        } else {
            // final: out = relu(D + b3) @ W4 + b4, shuffle + smem reduction.
            // oacc overlaid on each group's OWN (dead) W ring region.
            float* oacc_g = (float*)(smem + WRING_OFF + grp * GRING);
            float sres[4][3];
#pragma unroll
            for (int ii = 0; ii < 4; ii++)
#pragma unroll
                for (int o = 0; o < 3; o++) sres[ii][o] = 0.0f;
#pragma unroll
            for (int nt = 0; nt < 8; nt++) {
#pragma unroll
                for (int e = 0; e < 2; e++) {
                    const int col = grp * 64 + nt * 8 + (lane & 3) * 2 + e;
                    const float bb = bl_bias[col];
                    const float w40 = w4_s[col * 3 + 0];
                    const float w41 = w4_s[col * 3 + 1];
                    const float w42 = w4_s[col * 3 + 2];
                    const float h0 = fmaxf(acc[0][nt][e] + bb, 0.0f);
                    const float h1 = fmaxf(acc[0][nt][2 + e] + bb, 0.0f);
                    const float h2 = fmaxf(acc[1][nt][e] + bb, 0.0f);
                    const float h3 = fmaxf(acc[1][nt][2 + e] + bb, 0.0f);
                    sres[0][0] = fmaf(h0, w40, sres[0][0]); sres[0][1] = fmaf(h0, w41, sres[0][1]); sres[0][2] = fmaf(h0, w42, sres[0][2]);
                    sres[1][0] = fmaf(h1, w40, sres[1][0]); sres[1][1] = fmaf(h1, w41, sres[1][1]); sres[1][2] = fmaf(h1, w42, sres[1][2]);
                    sres[2][0] = fmaf(h2, w40, sres[2][0]); sres[2][1] = fmaf(h2, w41, sres[2][1]); sres[2][2] = fmaf(h2, w42, sres[2][2]);
                    sres[3][0] = fmaf(h3, w40, sres[3][0]); sres[3][1] = fmaf(h3, w41, sres[3][1]); sres[3][2] = fmaf(h3, w42, sres[3][2]);
                }
            }
#pragma unroll
            for (int ii = 0; ii < 4; ii++)
#pragma unroll
                for (int o = 0; o < 3; o++) {
                    float v = sres[ii][o];
                    v += __shfl_xor_sync(0xffffffff, v, 1);
                    v += __shfl_xor_sync(0xffffffff, v, 2);
                    sres[ii][o] = v;
                }
            if ((lane & 3) == 0) {
                const int rbase = wm * 32 + (lane >> 2);
#pragma unroll
                for (int ii = 0; ii < 4; ii++) {
                    const int row = rbase + ii * 8;
#pragma unroll
                    for (int o = 0; o < 3; o++)
                        oacc_g[row * 3 + o] = sres[ii][o];
                }
            }
            __syncthreads();
            if (tid < 128) {
                const float* o0p = (const float*)(smem + WRING_OFF);
                const float* o1p = (const float*)(smem + WRING_OFF + GRING);
                const float* o2p = (const float*)(smem + WRING_OFF + 2 * GRING);
                const float* o3p = (const float*)(smem + WRING_OFF + 3 * GRING);
                const float o0 = o0p[tid * 3]     + o1p[tid * 3]     + o2p[tid * 3]     + o3p[tid * 3]     + b4_s[0];
                const float o1 = o0p[tid * 3 + 1] + o1p[tid * 3 + 1] + o2p[tid * 3 + 1] + o3p[tid * 3 + 1] + b4_s[1];
                const float o2 = o0p[tid * 3 + 2] + o1p[tid * 3 + 2] + o2p[tid * 3 + 2] + o3p[tid * 3 + 2] + b4_s[2];
                const size_t base = (size_t)(b * 3) * (HQv * WQv) + (size_t)yq * WQv + xq;
                out[base]                           = o0;
                out[base + (size_t)(HQv * WQv)]     = o1;
                out[base + (size_t)(2 * HQv * WQv)] = o2;
            }
        }
    }
}

// ---------------------------------------------------------------------------
extern "C" void kernel_launch(void* const* d_in, const int* in_sizes, int n_in,
                              void* d_out, int out_size)
{
    const float* x     = (const float*)d_in[0];
    const float* coord = (const float*)d_in[1];
    const float* cell  = (const float*)d_in[2];
    const float* lr    = (const float*)d_in[3];
    const float* W0    = (const float*)d_in[4];
    const float* b0    = (const float*)d_in[5];
    const float* W1    = (const float*)d_in[6];
    const float* b1    = (const float*)d_in[7];
    const float* W2    = (const float*)d_in[8];
    const float* b2    = (const float*)d_in[9];
    const float* W3    = (const float*)d_in[10];
    const float* b3    = (const float*)d_in[11];
    const float* W4    = (const float*)d_in[12];
    const float* b4    = (const float*)d_in[13];
    float* out = (float*)d_out;

    liif_prep_kernel<<<896, 256>>>(W0, W1, W2, W3);

    const int P = out_size / 3;      // 589824
    const int nblk = P / MT;         // 4608

    cudaFuncSetAttribute(liif_hmma_kernel,
                         cudaFuncAttributeMaxDynamicSharedMemorySize, SMEM_TOTAL);
    liif_hmma_kernel<<<nblk, NTH, SMEM_TOTAL>>>(
        x, coord, cell, lr, b0, b1, b2, b3, W4, b4, out);
}

// round 15
// speedup vs baseline: 1.5137x; 1.5137x over previous
#include <cuda_runtime.h>
#include <cuda_fp16.h>
#include <cstdint>

// ============================================================================
// LIIF sampler, single-pass fp16 mma.sync. Round 15: R9 exactly, except L0's
// two chunks (64+16) merged into one 80-row chunk -> 13 phases instead of 14.
// Same 3-deep per-group W ring, same issue-(g+2)/wait_group-1 discipline.
// ============================================================================

#define HQv 384
#define WQv 384
#define HFv 48
#define WFv 48

#define MT  128
#define NTH 512

// smem layout (bytes)
#define A_OFF 0                            // 128*528 = 67584
#define WRING_OFF 67584
#define GBUF  11520                        // 80 rows * 144B
#define GRING (3 * GBUF)                   // 34560 per group (3-deep)
#define BIAS_OFF (WRING_OFF + 4 * GRING)   // 205824
#define W4_OFF   (BIAS_OFF + 4096)         // 209920
#define B4_OFF   (W4_OFF + 3072)           // 212992
#define OACC_OFF (B4_OFF + 16)             // 213008 : [4][128][3] fp32
#define SMEM_TOTAL (OACC_OFF + 6144)       // 219152

// weight blob: per layer one fp16 plane [kpad][256]. kpad: L0=128, L1..3=256.
__device__ __align__(128) unsigned char g_wblob[458752];
__constant__ int c_lbase[4] = {0, 65536, 196608, 327680};

// ---------------------------------------------------------------------------
__device__ __forceinline__ uint32_t smem_u32(const void* p) {
    uint32_t a;
    asm("{ .reg .u64 t; cvta.to.shared.u64 t, %1; cvt.u32.u64 %0, t; }"
        : "=r"(a) : "l"(p));
    return a;
}
__device__ __forceinline__ void ldsm4(uint32_t* r, uint32_t a) {
    asm volatile("ldmatrix.sync.aligned.m8n8.x4.shared.b16 {%0,%1,%2,%3}, [%4];"
                 : "=r"(r[0]), "=r"(r[1]), "=r"(r[2]), "=r"(r[3]) : "r"(a));
}
__device__ __forceinline__ void ldsm4t(uint32_t* r, uint32_t a) {
    asm volatile("ldmatrix.sync.aligned.m8n8.x4.trans.shared.b16 {%0,%1,%2,%3}, [%4];"
                 : "=r"(r[0]), "=r"(r[1]), "=r"(r[2]), "=r"(r[3]) : "r"(a));
}
__device__ __forceinline__ void mma16816h(float* d, const uint32_t* a,
                                          uint32_t b0, uint32_t b1) {
    asm volatile(
        "mma.sync.aligned.m16n8k16.row.col.f32.f16.f16.f32 "
        "{%0,%1,%2,%3}, {%4,%5,%6,%7}, {%8,%9}, {%0,%1,%2,%3};"
        : "+f"(d[0]), "+f"(d[1]), "+f"(d[2]), "+f"(d[3])
        : "r"(a[0]), "r"(a[1]), "r"(a[2]), "r"(a[3]), "r"(b0), "r"(b1));
}
__device__ __forceinline__ void cpasync16(uint32_t dst, const void* src) {
    asm volatile("cp.async.cg.shared.global [%0], [%1], 16;"
                 :: "r"(dst), "l"(src) : "memory");
}
__device__ __forceinline__ void cp_commit() {
    asm volatile("cp.async.commit_group;" ::: "memory");
}
__device__ __forceinline__ uint32_t cvt1h(float a, float b) {
    __half ah = __float2half_rn(a), bh = __float2half_rn(b);
    return (uint32_t)__half_as_ushort(ah) | ((uint32_t)__half_as_ushort(bh) << 16);
}

// global chunk index g (0..12): g==0 is L0 (80 rows); g 1..12 are 64-row
// chunks of layers 1..3 (4 chunks each).
__device__ __forceinline__ void chunk_of(int g, int& layer, int& c, int& rows) {
    if (g == 0) { layer = 0; c = 0; rows = 80; }
    else { layer = 1 + (g - 1) / 4; c = (g - 1) & 3; rows = 64; }
}

// stage this group's 64-col slice of chunk g into ring buffer (g % 3)
__device__ __forceinline__ void issue_group_chunk(uint32_t sb, int tid, int grp, int g) {
    int layer, c, rows;
    chunk_of(g, layer, c, rows);
    const int bsel = g % 3;
    const unsigned char* src0 = g_wblob + c_lbase[layer]
                              + (size_t)c * 64 * 512 + (size_t)grp * 128;
    const int t = tid & 127;
#pragma unroll
    for (int it = 0; it < 5; it++) {
        const int i = t + it * 128;   // 0..639
        const int r = i >> 3, s = i & 7;
        if (r < rows)
            cpasync16(sb + WRING_OFF + grp * GRING + bsel * GBUF + r * 144 + s * 16,
                      src0 + (size_t)r * 512 + s * 16);
    }
    cp_commit();
}

// ---------------------------------------------------------------------------
// Prep: W0..W3 fp32 -> single fp16 plane each.
// ---------------------------------------------------------------------------
__global__ void liif_prep_kernel(const float* __restrict__ W0, const float* __restrict__ W1,
                                 const float* __restrict__ W2, const float* __restrict__ W3)
{
    const int row = blockIdx.x;
    const int n = threadIdx.x;
    int layer, k;
    if (row < 128) { layer = 0; k = row; }
    else { layer = 1 + (row - 128) / 256; k = (row - 128) & 255; }
    const float* W = (layer == 0) ? W0 : (layer == 1) ? W1 : (layer == 2) ? W2 : W3;
    const int Kl = (layer == 0) ? 71 : 256;
    const float val = (k < Kl) ? W[k * 256 + n] : 0.0f;
    *(unsigned short*)(g_wblob + c_lbase[layer] + (size_t)k * 512 + n * 2) =
        __half_as_ushort(__float2half_rn(val));
}

// ---------------------------------------------------------------------------
__global__ __launch_bounds__(NTH, 1)
void liif_hmma_kernel(
    const float* __restrict__ x, const float* __restrict__ coord,
    const float* __restrict__ cell, const float* __restrict__ lr,
    const float* __restrict__ b0, const float* __restrict__ b1,
    const float* __restrict__ b2, const float* __restrict__ b3,
    const float* __restrict__ W4, const float* __restrict__ b4,
    float* __restrict__ out)
{
    extern __shared__ __align__(16) char smem[];
    const uint32_t sb = smem_u32(smem);
    const int tid = threadIdx.x;
    const int lane = tid & 31;
    const int wid = tid >> 5;
    const int wm = wid & 3;     // 4 warps along M (32 rows each)
    const int grp = wid >> 2;   // column group 0..3 (64 cols); 1 warp/SMSP/group

    float* bias_s = (float*)(smem + BIAS_OFF);
    float* w4_s   = (float*)(smem + W4_OFF);
    float* b4_s   = (float*)(smem + B4_OFF);
    float* oacc   = (float*)(smem + OACC_OFF);

    // prefetch this group's slices of chunks 0 and 1 (land during gather)
    issue_group_chunk(sb, tid, grp, 0);
    issue_group_chunk(sb, tid, grp, 1);

    // stage biases + W4
    if (tid < 256) {
        bias_s[tid] = b0[tid]; bias_s[256 + tid] = b1[tid];
        bias_s[512 + tid] = b2[tid]; bias_s[768 + tid] = b3[tid];
    }
    for (int i = tid; i < 768; i += NTH) w4_s[i] = W4[i];
    if (tid < 3) b4_s[tid] = b4[tid];

    // ---- gather -> A0 (fp16, 128 point-rows, stride 528B) ----
    const int p  = tid & 127;
    const int q  = tid >> 7;   // 0..3
    const int gp = blockIdx.x * MT + p;
    const int b  = gp / (HQv * WQv);
    const int rem = gp % (HQv * WQv);
    const int yq = rem / WQv, xq = rem % WQv;
    const float gy = coord[((size_t)(b * HQv + yq) * WQv + xq) * 2 + 0];
    const float gx = coord[((size_t)(b * HQv + yq) * WQv + xq) * 2 + 1];

    float tx = __fmul_rn(__fadd_rn(__fmul_rn(__fadd_rn(gx, 1.0f), (float)WFv), -1.0f), 0.5f);
    float ty = __fmul_rn(__fadd_rn(__fmul_rn(__fadd_rn(gy, 1.0f), (float)HFv), -1.0f), 0.5f);
    const int ixn = (int)rintf(tx);
    const int iyn = (int)rintf(ty);
    const bool valid = (ixn >= 0) && (ixn < WFv) && (iyn >= 0) && (iyn < HFv);
    const int ixc = min(max(ixn, 0), WFv - 1);
    const int iyc = min(max(iyn, 0), HFv - 1);

    if (q < 2) {   // channels q*32 .. q*32+31
        const float* xb = x + (size_t)b * 64 * (HFv * WFv) + (size_t)iyc * WFv + ixc;
        char* rh = smem + A_OFF + (size_t)p * 528 + q * 64;
#pragma unroll
        for (int j = 0; j < 16; j++) {
            const int c0 = q * 32 + 2 * j;
            const float f0 = valid ? xb[(size_t)c0 * (HFv * WFv)] : 0.0f;
            const float f1 = valid ? xb[(size_t)(c0 + 1) * (HFv * WFv)] : 0.0f;
            *(uint32_t*)(rh + j * 4) = cvt1h(f0, f1);
        }
    } else if (q == 2) {  // scalar features -> cols 64..79 (kpad=80)
        float qy = 0.0f, qx = 0.0f;
        if (valid) {
            qy = __fadd_rn(__fdiv_rn(__fadd_rn(__fmul_rn(2.0f, (float)iyc), 1.0f), (float)HFv), -1.0f);
            qx = __fadd_rn(__fdiv_rn(__fadd_rn(__fmul_rn(2.0f, (float)ixc), 1.0f), (float)WFv), -1.0f);
        }
        float vals[16];
#pragma unroll
        for (int i = 0; i < 16; i++) vals[i] = 0.0f;
        vals[0] = __fmul_rn(__fadd_rn(gy, -qy), (float)HFv);
        vals[1] = __fmul_rn(__fadd_rn(gx, -qx), (float)WFv);
        vals[2] = __fmul_rn(cell[b * 2 + 0], (float)HFv);
        vals[3] = __fmul_rn(cell[b * 2 + 1], (float)WFv);
        const float rx = 1.0f / (float)HFv, ry = 1.0f / (float)WFv;
        const float lo_c = -1.0f + 1e-6f, hi_c = 1.0f - 1e-6f;
        float s[3][4];
        int j = 0;
#pragma unroll
        for (int a = 0; a < 2; a++) {
#pragma unroll
            for (int c2 = 0; c2 < 2; c2++) {
                const float vx = a ? 1.0f : -1.0f;
                const float vy = c2 ? 1.0f : -1.0f;
                float cy = __fadd_rn(__fadd_rn(gy, __fmul_rn(vx, rx)), 1e-6f);
                float cx = __fadd_rn(__fadd_rn(gx, __fmul_rn(vy, ry)), 1e-6f);
                cy = fminf(fmaxf(cy, lo_c), hi_c);
                cx = fminf(fmaxf(cx, lo_c), hi_c);
                float fx = __fmul_rn(__fadd_rn(__fmul_rn(__fadd_rn(cx, 1.0f), (float)WFv), -1.0f), 0.5f);
                float fy = __fmul_rn(__fadd_rn(__fmul_rn(__fadd_rn(cy, 1.0f), (float)HFv), -1.0f), 0.5f);
                int jx = min(max((int)rintf(fx), 0), WFv - 1);
                int jy = min(max((int)rintf(fy), 0), HFv - 1);
#pragma unroll
                for (int ch = 0; ch < 3; ch++)
                    s[ch][j] = lr[((size_t)(b * 3 + ch) * HFv + jy) * WFv + jx];
                j++;
            }
        }
#pragma unroll
        for (int ch = 0; ch < 3; ch++) {
            const float m = 0.25f * (s[ch][0] + s[ch][1] + s[ch][2] + s[ch][3]);
            float v = 0.0f;
#pragma unroll
            for (int qq = 0; qq < 4; qq++) { const float d = s[ch][qq] - m; v += d * d; }
            vals[4 + ch] = sqrtf(v * (1.0f / 3.0f));
        }
        char* rh = smem + A_OFF + (size_t)p * 528 + 128;
#pragma unroll
        for (int k = 0; k < 8; k++)
            *(uint32_t*)(rh + k * 4) = cvt1h(vals[2 * k], vals[2 * k + 1]);
    }
    __syncthreads();

    // ---- 4 MMA layers, group-decoupled phases, 3-deep W ring, 13 chunks ----
    float acc[2][8][4];
    const uint32_t aRowByte = (uint32_t)(wm * 32 + (lane & 15)) * 528 + (lane >> 4) * 16;
    const uint32_t wRowByte = (uint32_t)(lane & 15) * 144;
    const uint32_t wColByte = (uint32_t)(lane >> 4) * 16;
    const uint32_t wbg = sb + WRING_OFF + grp * GRING;
    const uint32_t barid = 1 + grp;

    int g = 0;  // global chunk index (0..12)
#pragma unroll 1
    for (int layer = 0; layer < 4; layer++) {
        const int nch = (layer == 0) ? 1 : 4;
#pragma unroll
        for (int mt = 0; mt < 2; mt++)
#pragma unroll
            for (int nt = 0; nt < 8; nt++)
#pragma unroll
                for (int e = 0; e < 4; e++) acc[mt][nt][e] = 0.0f;

#pragma unroll 1
        for (int c = 0; c < nch; c++, g++) {
            if (g < 12) asm volatile("cp.async.wait_group 1;" ::: "memory");
            else        asm volatile("cp.async.wait_group 0;" ::: "memory");
            asm volatile("bar.sync %0, 128;" :: "r"(barid) : "memory");
            if (g + 2 < 13) issue_group_chunk(sb, tid, grp, g + 2);

            const uint32_t wb = wbg + (g % 3) * GBUF;
            const uint32_t aBase = sb + A_OFF + aRowByte + (uint32_t)(c * 64) * 2;
            const uint32_t wBase = wb + wRowByte + wColByte;
            const int ks = (g == 0) ? 5 : 4;   // L0: 80 rows = 5 k-steps
#pragma unroll 1
            for (int kk = 0; kk < ks; kk++) {
                const uint32_t kByte = (uint32_t)(kk * 16) * 2;
                uint32_t ah[2][4];
                ldsm4(ah[0], aBase + kByte);
                ldsm4(ah[1], aBase + 16 * 528 + kByte);
#pragma unroll
                for (int ng = 0; ng < 4; ng++) {
                    const uint32_t bo = (uint32_t)(kk * 16) * 144 + (uint32_t)ng * 32;
                    uint32_t w[4];
                    ldsm4t(w, wBase + bo);
                    mma16816h(acc[0][2 * ng],     ah[0], w[0], w[1]);
                    mma16816h(acc[0][2 * ng + 1], ah[0], w[2], w[3]);
                    mma16816h(acc[1][2 * ng],     ah[1], w[0], w[1]);
                    mma16816h(acc[1][2 * ng + 1], ah[1], w[2], w[3]);
                }
            }
        }

        __syncthreads();   // all groups done reading A
        const float* bl_bias = bias_s + layer * 256;
        if (layer < 3) {
            // epilogue: relu(D+b) -> fp16 back into A (in place)
#pragma unroll
            for (int mt = 0; mt < 2; mt++) {
#pragma unroll
                for (int nt = 0; nt < 8; nt++) {
                    const int r0 = wm * 32 + mt * 16 + (lane >> 2);
                    const int c0 = grp * 64 + nt * 8 + (lane & 3) * 2;
                    const float bb0 = bl_bias[c0], bb1 = bl_bias[c0 + 1];
                    const float h00 = fmaxf(acc[mt][nt][0] + bb0, 0.0f);
                    const float h01 = fmaxf(acc[mt][nt][1] + bb1, 0.0f);
                    const float h10 = fmaxf(acc[mt][nt][2] + bb0, 0.0f);
                    const float h11 = fmaxf(acc[mt][nt][3] + bb1, 0.0f);
                    *(uint32_t*)(smem + A_OFF + (size_t)r0 * 528 + c0 * 2) = cvt1h(h00, h01);
                    *(uint32_t*)(smem + A_OFF + (size_t)(r0 + 8) * 528 + c0 * 2) = cvt1h(h10, h11);
                }
            }
            __syncthreads();   // A ready for next layer (all groups)
        } else {
            // final: out = relu(D + b3) @ W4 + b4, shuffle + smem reduction
            float sres[4][3];
#pragma unroll
            for (int ii = 0; ii < 4; ii++)
#pragma unroll
                for (int o = 0; o < 3; o++) sres[ii][o] = 0.0f;
#pragma unroll
            for (int nt = 0; nt < 8; nt++) {
#pragma unroll
                for (int e = 0; e < 2; e++) {
                    const int col = grp * 64 + nt * 8 + (lane & 3) * 2 + e;
                    const float bb = bl_bias[col];
                    const float w40 = w4_s[col * 3 + 0];
                    const float w41 = w4_s[col * 3 + 1];
                    const float w42 = w4_s[col * 3 + 2];
                    const float h0 = fmaxf(acc[0][nt][e] + bb, 0.0f);
                    const float h1 = fmaxf(acc[0][nt][2 + e] + bb, 0.0f);
                    const float h2 = fmaxf(acc[1][nt][e] + bb, 0.0f);
                    const float h3 = fmaxf(acc[1][nt][2 + e] + bb, 0.0f);
                    sres[0][0] = fmaf(h0, w40, sres[0][0]); sres[0][1] = fmaf(h0, w41, sres[0][1]); sres[0][2] = fmaf(h0, w42, sres[0][2]);
                    sres[1][0] = fmaf(h1, w40, sres[1][0]); sres[1][1] = fmaf(h1, w41, sres[1][1]); sres[1][2] = fmaf(h1, w42, sres[1][2]);
                    sres[2][0] = fmaf(h2, w40, sres[2][0]); sres[2][1] = fmaf(h2, w41, sres[2][1]); sres[2][2] = fmaf(h2, w42, sres[2][2]);
                    sres[3][0] = fmaf(h3, w40, sres[3][0]); sres[3][1] = fmaf(h3, w41, sres[3][1]); sres[3][2] = fmaf(h3, w42, sres[3][2]);
                }
            }
#pragma unroll
            for (int ii = 0; ii < 4; ii++)
#pragma unroll
                for (int o = 0; o < 3; o++) {
                    float v = sres[ii][o];
                    v += __shfl_xor_sync(0xffffffff, v, 1);
                    v += __shfl_xor_sync(0xffffffff, v, 2);
                    sres[ii][o] = v;
                }
            if ((lane & 3) == 0) {
                const int rbase = wm * 32 + (lane >> 2);
#pragma unroll
                for (int ii = 0; ii < 4; ii++) {
                    const int row = rbase + ii * 8;
#pragma unroll
                    for (int o = 0; o < 3; o++)
                        oacc[(grp * 128 + row) * 3 + o] = sres[ii][o];
                }
            }
            __syncthreads();
            if (tid < 128) {
                const float o0 = oacc[tid * 3] + oacc[(128 + tid) * 3]
                               + oacc[(256 + tid) * 3] + oacc[(384 + tid) * 3] + b4_s[0];
                const float o1 = oacc[tid * 3 + 1] + oacc[(128 + tid) * 3 + 1]
                               + oacc[(256 + tid) * 3 + 1] + oacc[(384 + tid) * 3 + 1] + b4_s[1];
                const float o2 = oacc[tid * 3 + 2] + oacc[(128 + tid) * 3 + 2]
                               + oacc[(256 + tid) * 3 + 2] + oacc[(384 + tid) * 3 + 2] + b4_s[2];
                const size_t base = (size_t)(b * 3) * (HQv * WQv) + (size_t)yq * WQv + xq;
                out[base]                           = o0;
                out[base + (size_t)(HQv * WQv)]     = o1;
                out[base + (size_t)(2 * HQv * WQv)] = o2;
            }
        }
    }
}

// ---------------------------------------------------------------------------
extern "C" void kernel_launch(void* const* d_in, const int* in_sizes, int n_in,
                              void* d_out, int out_size)
{
    const float* x     = (const float*)d_in[0];
    const float* coord = (const float*)d_in[1];
    const float* cell  = (const float*)d_in[2];
    const float* lr    = (const float*)d_in[3];
    const float* W0    = (const float*)d_in[4];
    const float* b0    = (const float*)d_in[5];
    const float* W1    = (const float*)d_in[6];
    const float* b1    = (const float*)d_in[7];
    const float* W2    = (const float*)d_in[8];
    const float* b2    = (const float*)d_in[9];
    const float* W3    = (const float*)d_in[10];
    const float* b3    = (const float*)d_in[11];
    const float* W4    = (const float*)d_in[12];
    const float* b4    = (const float*)d_in[13];
    float* out = (float*)d_out;

    liif_prep_kernel<<<896, 256>>>(W0, W1, W2, W3);

    const int P = out_size / 3;      // 589824
    const int nblk = P / MT;         // 4608

    cudaFuncSetAttribute(liif_hmma_kernel,
                         cudaFuncAttributeMaxDynamicSharedMemorySize, SMEM_TOTAL);
    liif_hmma_kernel<<<nblk, NTH, SMEM_TOTAL>>>(
        x, coord, cell, lr, b0, b1, b2, b3, W4, b4, out);
}

// round 16
// speedup vs baseline: 1.6810x; 1.1105x over previous
#include <cuda_runtime.h>
#include <cuda_fp16.h>
#include <cstdint>

// ============================================================================
// LIIF sampler, single-pass fp16 mma.sync (A fp16, W fp16, fp32 accum).
// FINAL (= Round 9, best measured 884.8us): per-N-group decoupled pipelines,
// 3-deep W ring with issue-(g+2)/wait_group-1, single A plane, exact fp32
// final layer. Verified rel_err 6.03e-4 (< 1e-3 gate).
// ============================================================================

#define HQv 384
#define WQv 384
#define HFv 48
#define WFv 48

#define MT  128
#define NTH 512

// smem layout (bytes)
#define A_OFF 0                            // 128*528 = 67584
#define WRING_OFF 67584
#define GBUF  9216                         // 64 rows * 144B
#define GRING (3 * GBUF)                   // 27648 per group (3-deep)
#define BIAS_OFF (WRING_OFF + 4 * GRING)   // 178176
#define W4_OFF   (BIAS_OFF + 4096)         // 182272
#define B4_OFF   (W4_OFF + 3072)           // 185344
#define OACC_OFF (B4_OFF + 16)             // 185360 : [4][128][3] fp32
#define SMEM_TOTAL (OACC_OFF + 6144)       // 191504

// weight blob: per layer one fp16 plane [kpad][256]. kpad: L0=128, L1..3=256.
__device__ __align__(128) unsigned char g_wblob[458752];
__constant__ int c_lbase[4] = {0, 65536, 196608, 327680};

// ---------------------------------------------------------------------------
__device__ __forceinline__ uint32_t smem_u32(const void* p) {
    uint32_t a;
    asm("{ .reg .u64 t; cvta.to.shared.u64 t, %1; cvt.u32.u64 %0, t; }"
        : "=r"(a) : "l"(p));
    return a;
}
__device__ __forceinline__ void ldsm4(uint32_t* r, uint32_t a) {
    asm volatile("ldmatrix.sync.aligned.m8n8.x4.shared.b16 {%0,%1,%2,%3}, [%4];"
                 : "=r"(r[0]), "=r"(r[1]), "=r"(r[2]), "=r"(r[3]) : "r"(a));
}
__device__ __forceinline__ void ldsm4t(uint32_t& r0, uint32_t& r1, uint32_t& r2,
                                       uint32_t& r3, uint32_t a) {
    asm volatile("ldmatrix.sync.aligned.m8n8.x4.trans.shared.b16 {%0,%1,%2,%3}, [%4];"
                 : "=r"(r0), "=r"(r1), "=r"(r2), "=r"(r3) : "r"(a));
}
__device__ __forceinline__ void mma16816h(float* d, const uint32_t* a,
                                          uint32_t b0, uint32_t b1) {
    asm volatile(
        "mma.sync.aligned.m16n8k16.row.col.f32.f16.f16.f32 "
        "{%0,%1,%2,%3}, {%4,%5,%6,%7}, {%8,%9}, {%0,%1,%2,%3};"
        : "+f"(d[0]), "+f"(d[1]), "+f"(d[2]), "+f"(d[3])
        : "r"(a[0]), "r"(a[1]), "r"(a[2]), "r"(a[3]), "r"(b0), "r"(b1));
}
__device__ __forceinline__ void cpasync16(uint32_t dst, const void* src) {
    asm volatile("cp.async.cg.shared.global [%0], [%1], 16;"
                 :: "r"(dst), "l"(src) : "memory");
}
__device__ __forceinline__ void cp_commit() {
    asm volatile("cp.async.commit_group;" ::: "memory");
}
__device__ __forceinline__ uint32_t cvt1h(float a, float b) {
    __half ah = __float2half_rn(a), bh = __float2half_rn(b);
    return (uint32_t)__half_as_ushort(ah) | ((uint32_t)__half_as_ushort(bh) << 16);
}

// global chunk index g (0..13): g==1 is the 16-row tail of L0 (kpad 80).
__device__ __forceinline__ void chunk_of(int g, int& layer, int& c) {
    if (g < 2) { layer = 0; c = g; }
    else { layer = 1 + (g - 2) / 4; c = (g - 2) & 3; }
}

// stage this group's 64-col slice of chunk g into ring buffer (g % 3)
__device__ __forceinline__ void issue_group_chunk(uint32_t sb, int tid, int grp, int g) {
    int layer, c;
    chunk_of(g, layer, c);
    const int rows = (g == 1) ? 16 : 64;
    const int bsel = g % 3;
    const unsigned char* src0 = g_wblob + c_lbase[layer]
                              + (size_t)c * 64 * 512 + (size_t)grp * 128;
    const int t = tid & 127;
#pragma unroll
    for (int it = 0; it < 4; it++) {
        const int i = t + it * 128;   // 0..511
        const int r = i >> 3, s = i & 7;
        if (r < rows)
            cpasync16(sb + WRING_OFF + grp * GRING + bsel * GBUF + r * 144 + s * 16,
                      src0 + (size_t)r * 512 + s * 16);
    }
    cp_commit();
}

// ---------------------------------------------------------------------------
// Prep: W0..W3 fp32 -> single fp16 plane each.
// ---------------------------------------------------------------------------
__global__ void liif_prep_kernel(const float* __restrict__ W0, const float* __restrict__ W1,
                                 const float* __restrict__ W2, const float* __restrict__ W3)
{
    const int row = blockIdx.x;
    const int n = threadIdx.x;
    int layer, k;
    if (row < 128) { layer = 0; k = row; }
    else { layer = 1 + (row - 128) / 256; k = (row - 128) & 255; }
    const float* W = (layer == 0) ? W0 : (layer == 1) ? W1 : (layer == 2) ? W2 : W3;
    const int Kl = (layer == 0) ? 71 : 256;
    const float val = (k < Kl) ? W[k * 256 + n] : 0.0f;
    *(unsigned short*)(g_wblob + c_lbase[layer] + (size_t)k * 512 + n * 2) =
        __half_as_ushort(__float2half_rn(val));
}

// ---------------------------------------------------------------------------
__global__ __launch_bounds__(NTH, 1)
void liif_hmma_kernel(
    const float* __restrict__ x, const float* __restrict__ coord,
    const float* __restrict__ cell, const float* __restrict__ lr,
    const float* __restrict__ b0, const float* __restrict__ b1,
    const float* __restrict__ b2, const float* __restrict__ b3,
    const float* __restrict__ W4, const float* __restrict__ b4,
    float* __restrict__ out)
{
    extern __shared__ __align__(16) char smem[];
    const uint32_t sb = smem_u32(smem);
    const int tid = threadIdx.x;
    const int lane = tid & 31;
    const int wid = tid >> 5;
    const int wm = wid & 3;     // 4 warps along M (32 rows each)
    const int grp = wid >> 2;   // column group 0..3 (64 cols); 1 warp/SMSP/group

    float* bias_s = (float*)(smem + BIAS_OFF);
    float* w4_s   = (float*)(smem + W4_OFF);
    float* b4_s   = (float*)(smem + B4_OFF);
    float* oacc   = (float*)(smem + OACC_OFF);

    // prefetch this group's slices of chunks 0 and 1 (land during gather)
    issue_group_chunk(sb, tid, grp, 0);
    issue_group_chunk(sb, tid, grp, 1);

    // stage biases + W4
    if (tid < 256) {
        bias_s[tid] = b0[tid]; bias_s[256 + tid] = b1[tid];
        bias_s[512 + tid] = b2[tid]; bias_s[768 + tid] = b3[tid];
    }
    for (int i = tid; i < 768; i += NTH) w4_s[i] = W4[i];
    if (tid < 3) b4_s[tid] = b4[tid];

    // ---- gather -> A0 (fp16, 128 point-rows, stride 528B) ----
    const int p  = tid & 127;
    const int q  = tid >> 7;   // 0..3
    const int gp = blockIdx.x * MT + p;
    const int b  = gp / (HQv * WQv);
    const int rem = gp % (HQv * WQv);
    const int yq = rem / WQv, xq = rem % WQv;
    const float gy = coord[((size_t)(b * HQv + yq) * WQv + xq) * 2 + 0];
    const float gx = coord[((size_t)(b * HQv + yq) * WQv + xq) * 2 + 1];

    float tx = __fmul_rn(__fadd_rn(__fmul_rn(__fadd_rn(gx, 1.0f), (float)WFv), -1.0f), 0.5f);
    float ty = __fmul_rn(__fadd_rn(__fmul_rn(__fadd_rn(gy, 1.0f), (float)HFv), -1.0f), 0.5f);
    const int ixn = (int)rintf(tx);
    const int iyn = (int)rintf(ty);
    const bool valid = (ixn >= 0) && (ixn < WFv) && (iyn >= 0) && (iyn < HFv);
    const int ixc = min(max(ixn, 0), WFv - 1);
    const int iyc = min(max(iyn, 0), HFv - 1);

    if (q < 2) {   // channels q*32 .. q*32+31
        const float* xb = x + (size_t)b * 64 * (HFv * WFv) + (size_t)iyc * WFv + ixc;
        char* rh = smem + A_OFF + (size_t)p * 528 + q * 64;
#pragma unroll
        for (int j = 0; j < 16; j++) {
            const int c0 = q * 32 + 2 * j;
            const float f0 = valid ? xb[(size_t)c0 * (HFv * WFv)] : 0.0f;
            const float f1 = valid ? xb[(size_t)(c0 + 1) * (HFv * WFv)] : 0.0f;
            *(uint32_t*)(rh + j * 4) = cvt1h(f0, f1);
        }
    } else if (q == 2) {  // scalar features -> cols 64..79 (kpad=80)
        float qy = 0.0f, qx = 0.0f;
        if (valid) {
            qy = __fadd_rn(__fdiv_rn(__fadd_rn(__fmul_rn(2.0f, (float)iyc), 1.0f), (float)HFv), -1.0f);
            qx = __fadd_rn(__fdiv_rn(__fadd_rn(__fmul_rn(2.0f, (float)ixc), 1.0f), (float)WFv), -1.0f);
        }
        float vals[16];
#pragma unroll
        for (int i = 0; i < 16; i++) vals[i] = 0.0f;
        vals[0] = __fmul_rn(__fadd_rn(gy, -qy), (float)HFv);
        vals[1] = __fmul_rn(__fadd_rn(gx, -qx), (float)WFv);
        vals[2] = __fmul_rn(cell[b * 2 + 0], (float)HFv);
        vals[3] = __fmul_rn(cell[b * 2 + 1], (float)WFv);
        const float rx = 1.0f / (float)HFv, ry = 1.0f / (float)WFv;
        const float lo_c = -1.0f + 1e-6f, hi_c = 1.0f - 1e-6f;
        float s[3][4];
        int j = 0;
#pragma unroll
        for (int a = 0; a < 2; a++) {
#pragma unroll
            for (int c2 = 0; c2 < 2; c2++) {
                const float vx = a ? 1.0f : -1.0f;
                const float vy = c2 ? 1.0f : -1.0f;
                float cy = __fadd_rn(__fadd_rn(gy, __fmul_rn(vx, rx)), 1e-6f);
                float cx = __fadd_rn(__fadd_rn(gx, __fmul_rn(vy, ry)), 1e-6f);
                cy = fminf(fmaxf(cy, lo_c), hi_c);
                cx = fminf(fmaxf(cx, lo_c), hi_c);
                float fx = __fmul_rn(__fadd_rn(__fmul_rn(__fadd_rn(cx, 1.0f), (float)WFv), -1.0f), 0.5f);
                float fy = __fmul_rn(__fadd_rn(__fmul_rn(__fadd_rn(cy, 1.0f), (float)HFv), -1.0f), 0.5f);
                int jx = min(max((int)rintf(fx), 0), WFv - 1);
                int jy = min(max((int)rintf(fy), 0), HFv - 1);
#pragma unroll
                for (int ch = 0; ch < 3; ch++)
                    s[ch][j] = lr[((size_t)(b * 3 + ch) * HFv + jy) * WFv + jx];
                j++;
            }
        }
#pragma unroll
        for (int ch = 0; ch < 3; ch++) {
            const float m = 0.25f * (s[ch][0] + s[ch][1] + s[ch][2] + s[ch][3]);
            float v = 0.0f;
#pragma unroll
            for (int qq = 0; qq < 4; qq++) { const float d = s[ch][qq] - m; v += d * d; }
            vals[4 + ch] = sqrtf(v * (1.0f / 3.0f));
        }
        char* rh = smem + A_OFF + (size_t)p * 528 + 128;
#pragma unroll
        for (int k = 0; k < 8; k++)
            *(uint32_t*)(rh + k * 4) = cvt1h(vals[2 * k], vals[2 * k + 1]);
    }
    __syncthreads();

    // ---- 4 MMA layers, group-decoupled phases, 3-deep W ring ----
    float acc[2][8][4];
    const uint32_t aRowByte = (uint32_t)(wm * 32 + (lane & 15)) * 528 + (lane >> 4) * 16;
    const uint32_t wRowByte = (uint32_t)(lane & 15) * 144;
    const uint32_t wColByte = (uint32_t)(lane >> 4) * 16;
    const uint32_t wbg = sb + WRING_OFF + grp * GRING;
    const uint32_t barid = 1 + grp;

    int g = 0;  // global chunk index (0..13)
#pragma unroll 1
    for (int layer = 0; layer < 4; layer++) {
        const int nch = (layer == 0) ? 2 : 4;
#pragma unroll
        for (int mt = 0; mt < 2; mt++)
#pragma unroll
            for (int nt = 0; nt < 8; nt++)
#pragma unroll
                for (int e = 0; e < 4; e++) acc[mt][nt][e] = 0.0f;

#pragma unroll 1
        for (int c = 0; c < nch; c++, g++) {
            if (g < 13) asm volatile("cp.async.wait_group 1;" ::: "memory");
            else        asm volatile("cp.async.wait_group 0;" ::: "memory");
            asm volatile("bar.sync %0, 128;" :: "r"(barid) : "memory");
            if (g + 2 < 14) issue_group_chunk(sb, tid, grp, g + 2);

            const uint32_t wb = wbg + (g % 3) * GBUF;
            const int ks = (g == 1) ? 1 : 4;   // L0 tail chunk: 16 rows
#pragma unroll 1
            for (int kk = 0; kk < ks; kk++) {
                const uint32_t kByte = (uint32_t)(c * 64 + kk * 16) * 2;
                uint32_t ah[2][4];
#pragma unroll
                for (int mt = 0; mt < 2; mt++)
                    ldsm4(ah[mt], sb + A_OFF + aRowByte + (uint32_t)(mt * 16) * 528 + kByte);
#pragma unroll
                for (int ng = 0; ng < 4; ng++) {
                    const uint32_t bo = wRowByte + (uint32_t)(kk * 16) * 144
                                      + wColByte + (uint32_t)ng * 32;
                    uint32_t w0, w1, w2, w3;
                    ldsm4t(w0, w1, w2, w3, wb + bo);
                    mma16816h(acc[0][2 * ng],     ah[0], w0, w1);
                    mma16816h(acc[0][2 * ng + 1], ah[0], w2, w3);
                    mma16816h(acc[1][2 * ng],     ah[1], w0, w1);
                    mma16816h(acc[1][2 * ng + 1], ah[1], w2, w3);
                }
            }
        }

        __syncthreads();   // all groups done reading A
        const float* bl_bias = bias_s + layer * 256;
        if (layer < 3) {
            // epilogue: relu(D+b) -> fp16 back into A (in place)
#pragma unroll
            for (int mt = 0; mt < 2; mt++) {
#pragma unroll
                for (int nt = 0; nt < 8; nt++) {
                    const int r0 = wm * 32 + mt * 16 + (lane >> 2);
                    const int c0 = grp * 64 + nt * 8 + (lane & 3) * 2;
                    const float bb0 = bl_bias[c0], bb1 = bl_bias[c0 + 1];
                    const float h00 = fmaxf(acc[mt][nt][0] + bb0, 0.0f);
                    const float h01 = fmaxf(acc[mt][nt][1] + bb1, 0.0f);
                    const float h10 = fmaxf(acc[mt][nt][2] + bb0, 0.0f);
                    const float h11 = fmaxf(acc[mt][nt][3] + bb1, 0.0f);
                    *(uint32_t*)(smem + A_OFF + (size_t)r0 * 528 + c0 * 2) = cvt1h(h00, h01);
                    *(uint32_t*)(smem + A_OFF + (size_t)(r0 + 8) * 528 + c0 * 2) = cvt1h(h10, h11);
                }
            }
            __syncthreads();   // A ready for next layer (all groups)
        } else {
            // final: out = relu(D + b3) @ W4 + b4, shuffle + smem reduction
            float sres[4][3];
#pragma unroll
            for (int ii = 0; ii < 4; ii++)
#pragma unroll
                for (int o = 0; o < 3; o++) sres[ii][o] = 0.0f;
#pragma unroll
            for (int nt = 0; nt < 8; nt++) {
#pragma unroll
                for (int e = 0; e < 2; e++) {
                    const int col = grp * 64 + nt * 8 + (lane & 3) * 2 + e;
                    const float bb = bl_bias[col];
                    const float w40 = w4_s[col * 3 + 0];
                    const float w41 = w4_s[col * 3 + 1];
                    const float w42 = w4_s[col * 3 + 2];
                    const float h0 = fmaxf(acc[0][nt][e] + bb, 0.0f);
                    const float h1 = fmaxf(acc[0][nt][2 + e] + bb, 0.0f);
                    const float h2 = fmaxf(acc[1][nt][e] + bb, 0.0f);
                    const float h3 = fmaxf(acc[1][nt][2 + e] + bb, 0.0f);
                    sres[0][0] = fmaf(h0, w40, sres[0][0]); sres[0][1] = fmaf(h0, w41, sres[0][1]); sres[0][2] = fmaf(h0, w42, sres[0][2]);
                    sres[1][0] = fmaf(h1, w40, sres[1][0]); sres[1][1] = fmaf(h1, w41, sres[1][1]); sres[1][2] = fmaf(h1, w42, sres[1][2]);
                    sres[2][0] = fmaf(h2, w40, sres[2][0]); sres[2][1] = fmaf(h2, w41, sres[2][1]); sres[2][2] = fmaf(h2, w42, sres[2][2]);
                    sres[3][0] = fmaf(h3, w40, sres[3][0]); sres[3][1] = fmaf(h3, w41, sres[3][1]); sres[3][2] = fmaf(h3, w42, sres[3][2]);
                }
            }
#pragma unroll
            for (int ii = 0; ii < 4; ii++)
#pragma unroll
                for (int o = 0; o < 3; o++) {
                    float v = sres[ii][o];
                    v += __shfl_xor_sync(0xffffffff, v, 1);
                    v += __shfl_xor_sync(0xffffffff, v, 2);
                    sres[ii][o] = v;
                }
            if ((lane & 3) == 0) {
                const int rbase = wm * 32 + (lane >> 2);
#pragma unroll
                for (int ii = 0; ii < 4; ii++) {
                    const int row = rbase + ii * 8;
#pragma unroll
                    for (int o = 0; o < 3; o++)
                        oacc[(grp * 128 + row) * 3 + o] = sres[ii][o];
                }
            }
            __syncthreads();
            if (tid < 128) {
                const float o0 = oacc[tid * 3] + oacc[(128 + tid) * 3]
                               + oacc[(256 + tid) * 3] + oacc[(384 + tid) * 3] + b4_s[0];
                const float o1 = oacc[tid * 3 + 1] + oacc[(128 + tid) * 3 + 1]
                               + oacc[(256 + tid) * 3 + 1] + oacc[(384 + tid) * 3 + 1] + b4_s[1];
                const float o2 = oacc[tid * 3 + 2] + oacc[(128 + tid) * 3 + 2]
                               + oacc[(256 + tid) * 3 + 2] + oacc[(384 + tid) * 3 + 2] + b4_s[2];
                const size_t base = (size_t)(b * 3) * (HQv * WQv) + (size_t)yq * WQv + xq;
                out[base]                           = o0;
                out[base + (size_t)(HQv * WQv)]     = o1;
                out[base + (size_t)(2 * HQv * WQv)] = o2;
            }
        }
    }
}

// ---------------------------------------------------------------------------
extern "C" void kernel_launch(void* const* d_in, const int* in_sizes, int n_in,
                              void* d_out, int out_size)
{
    const float* x     = (const float*)d_in[0];
    const float* coord = (const float*)d_in[1];
    const float* cell  = (const float*)d_in[2];
    const float* lr    = (const float*)d_in[3];
    const float* W0    = (const float*)d_in[4];
    const float* b0    = (const float*)d_in[5];
    const float* W1    = (const float*)d_in[6];
    const float* b1    = (const float*)d_in[7];
    const float* W2    = (const float*)d_in[8];
    const float* b2    = (const float*)d_in[9];
    const float* W3    = (const float*)d_in[10];
    const float* b3    = (const float*)d_in[11];
    const float* W4    = (const float*)d_in[12];
    const float* b4    = (const float*)d_in[13];
    float* out = (float*)d_out;

    liif_prep_kernel<<<896, 256>>>(W0, W1, W2, W3);

    const int P = out_size / 3;      // 589824
    const int nblk = P / MT;         // 4608

    cudaFuncSetAttribute(liif_hmma_kernel,
                         cudaFuncAttributeMaxDynamicSharedMemorySize, SMEM_TOTAL);
    liif_hmma_kernel<<<nblk, NTH, SMEM_TOTAL>>>(
        x, coord, cell, lr, b0, b1, b2, b3, W4, b4, out);
}